// round 5
// baseline (speedup 1.0000x reference)
#include <cuda_runtime.h>
#include <cstdint>

typedef unsigned long long ull;

#define PP   64
#define HH   256
#define BB   32
#define TT   128
#define LE   10
#define LD   118
#define K3H  768   // 3*H
#define PADU 18    // padded smem row width in ull (16 data + 2 pad), keeps 16B align

#define PRED_ELEMS (PP * BB * LD)
#define MU_OFF     PRED_ELEMS
#define LV_OFF     (PRED_ELEMS + BB * HH)

// ---- scratch (static device allocations) ----------------------------------
// +4*K3H pad: prefetch pipeline reads one 4-layer block past each section end.
__device__ float g_Wt_hh[PP * HH * K3H + 4 * K3H];   // [p][h][k]
__device__ float g_Wt_ih[PP * PP * K3H + 4 * K3H];   // [p][i][k]
__device__ float g_Xt[LD * PP * BB];                 // [l][i][b]
__device__ float g_xpe[LE * BB * K3H];               // [l][b][k]
__device__ float g_hT[BB * HH];
__device__ float g_z[BB * HH];

// ---- helpers --------------------------------------------------------------
__device__ __forceinline__ ull fma2(ull a, ull b, ull c) {
    ull d;
    asm("fma.rn.f32x2 %0, %1, %2, %3;" : "=l"(d) : "l"(a), "l"(b), "l"(c));
    return d;
}
__device__ __forceinline__ ull bcast2(float x) {
    ull d;
    asm("mov.b64 %0, {%1, %1};" : "=l"(d) : "f"(x));
    return d;
}
__device__ __forceinline__ void unpack2(ull v, float& x, float& y) {
    asm("mov.b64 {%0, %1}, %2;" : "=f"(x), "=f"(y) : "l"(v));
}
__device__ __forceinline__ float sigf(float x) {
    return __fdividef(1.0f, 1.0f + __expf(-x));
}
__device__ __forceinline__ float tfast(float x) {
    float e = __expf(2.0f * x);
    return 1.0f - __fdividef(2.0f, e + 1.0f);
}

// ---- K1: transpose Whh_d [p][k][h] -> g_Wt_hh [p][h][k] -------------------
__global__ void transpose_hh_kernel(const float* __restrict__ in) {
    __shared__ float tile[32][33];
    const int rows = K3H, cols = HH;
    const float* ip = in + (size_t)blockIdx.z * rows * cols;
    float* op = g_Wt_hh + (size_t)blockIdx.z * rows * cols;
    int c0 = blockIdx.x * 32, r0 = blockIdx.y * 32;
    int tx = threadIdx.x, ty = threadIdx.y;
#pragma unroll
    for (int dy = 0; dy < 32; dy += 8)
        tile[ty + dy][tx] = ip[(r0 + ty + dy) * cols + (c0 + tx)];
    __syncthreads();
#pragma unroll
    for (int dy = 0; dy < 32; dy += 8)
        op[(c0 + ty + dy) * rows + (r0 + tx)] = tile[tx][ty + dy];
}

// ---- K2: transpose Wih_d [p][k][i] -> g_Wt_ih [p][i][k] -------------------
__global__ void transpose_ih_kernel(const float* __restrict__ in) {
    __shared__ float tile[32][33];
    const int rows = K3H, cols = PP;
    const float* ip = in + (size_t)blockIdx.z * rows * cols;
    float* op = g_Wt_ih + (size_t)blockIdx.z * rows * cols;
    int c0 = blockIdx.x * 32, r0 = blockIdx.y * 32;
    int tx = threadIdx.x, ty = threadIdx.y;
#pragma unroll
    for (int dy = 0; dy < 32; dy += 8)
        tile[ty + dy][tx] = ip[(r0 + ty + dy) * cols + (c0 + tx)];
    __syncthreads();
#pragma unroll
    for (int dy = 0; dy < 32; dy += 8)
        op[(c0 + ty + dy) * rows + (r0 + tx)] = tile[tx][ty + dy];
}

// ---- K3: Xt[l][i][b] = (l==0 ? 0 : X[b][l+9][i]) --------------------------
__global__ void build_xt_kernel(const float* __restrict__ X) {
    int idx = blockIdx.x * blockDim.x + threadIdx.x;
    if (idx >= LD * PP * BB) return;
    int b = idx & 31;
    int r = idx >> 5;
    int i = r & 63;
    int l = r >> 6;
    g_Xt[idx] = (l == 0) ? 0.0f : X[b * (TT * PP) + (l + 9) * PP + i];
}

// ---- K4: encoder input projection -----------------------------------------
__global__ void xpe_kernel(const float* __restrict__ X,
                           const float* __restrict__ Wih_e,
                           const float* __restrict__ bih_e) {
    __shared__ float xr[PP];
    int b = blockIdx.x, l = blockIdx.y;
    int tid = threadIdx.x;  // 256
    if (tid < PP) xr[tid] = X[b * (TT * PP) + l * PP + tid];
    __syncthreads();
#pragma unroll
    for (int g = 0; g < 3; ++g) {
        int k = g * HH + tid;
        float a = bih_e[k];
        const float* w = Wih_e + k * PP;
#pragma unroll
        for (int i = 0; i < PP; i += 4) {
            float4 wv = *(const float4*)(w + i);
            a += wv.x * xr[i] + wv.y * xr[i + 1] + wv.z * xr[i + 2] + wv.w * xr[i + 3];
        }
        g_xpe[(l * BB + b) * K3H + k] = a;
    }
}

// ---- K5: encoder GRU scan -------------------------------------------------
__global__ void enc_kernel(const float* __restrict__ Whh_e,
                           const float* __restrict__ bhh_e) {
    __shared__ float hs[HH];
    int b = blockIdx.x, j = threadIdx.x;
    hs[j] = 0.0f;
    float bR = bhh_e[j], bZ = bhh_e[HH + j], bN = bhh_e[2 * HH + j];
    const float* wR = Whh_e + j * HH;
    const float* wZ = Whh_e + (HH + j) * HH;
    const float* wN = Whh_e + (2 * HH + j) * HH;
    __syncthreads();
    for (int l = 0; l < LE; ++l) {
        float aR = 0.f, aZ = 0.f, aN = 0.f;
#pragma unroll 8
        for (int h = 0; h < HH; h += 4) {
            float4 hv = *(const float4*)&hs[h];
            float4 r4 = *(const float4*)(wR + h);
            float4 z4 = *(const float4*)(wZ + h);
            float4 n4 = *(const float4*)(wN + h);
            aR += r4.x * hv.x + r4.y * hv.y + r4.z * hv.z + r4.w * hv.w;
            aZ += z4.x * hv.x + z4.y * hv.y + z4.z * hv.z + z4.w * hv.w;
            aN += n4.x * hv.x + n4.y * hv.y + n4.z * hv.z + n4.w * hv.w;
        }
        const float* xp = g_xpe + (l * BB + b) * K3H;
        float r = sigf(xp[j] + aR + bR);
        float z = sigf(xp[HH + j] + aZ + bZ);
        float n = tfast(xp[2 * HH + j] + r * (aN + bN));
        float hold = hs[j];
        __syncthreads();
        hs[j] = (1.0f - z) * n + z * hold;
        __syncthreads();
    }
    g_hT[b * HH + j] = hs[j];
}

// ---- K6: mu / log_var / z -------------------------------------------------
__global__ void muz_kernel(const float* __restrict__ Wmu,
                           const float* __restrict__ bmu,
                           const float* __restrict__ Wstd,
                           const float* __restrict__ bstd,
                           const float* __restrict__ eps,
                           float* __restrict__ out) {
    __shared__ float hs[HH];
    int b = blockIdx.x, j = threadIdx.x;
    hs[j] = g_hT[b * HH + j];
    __syncthreads();
    float am = bmu[j], as = bstd[j];
    const float* wm = Wmu + j * HH;
    const float* ws = Wstd + j * HH;
#pragma unroll 8
    for (int h = 0; h < HH; h += 4) {
        float4 hv = *(const float4*)&hs[h];
        float4 m4 = *(const float4*)(wm + h);
        float4 s4 = *(const float4*)(ws + h);
        am += m4.x * hv.x + m4.y * hv.y + m4.z * hv.z + m4.w * hv.w;
        as += s4.x * hv.x + s4.y * hv.y + s4.z * hv.z + s4.w * hv.w;
    }
    out[MU_OFF + b * HH + j] = am;
    out[LV_OFF + b * HH + j] = as;
    g_z[b * HH + j] = am + expf(0.5f * as) * eps[b * HH + j];
}

// ---- decoder inner-loop building blocks -----------------------------------
__device__ __forceinline__ void loadW(ull (&w)[12], const float* base) {
#pragma unroll
    for (int l = 0; l < 4; ++l) {
        const float* r = base + l * K3H;
        w[l * 3 + 0] = *(const ull*)(r);
        w[l * 3 + 1] = *(const ull*)(r + HH);
        w[l * 3 + 2] = *(const ull*)(r + 2 * HH);
    }
}

// src holds operands pre-duplicated as f32x2 (ull per (row, b)).
// All lanes of a warp read the same address -> smem broadcast (free).
__device__ __forceinline__ void comp4(const ull (&w)[12],
                                      const ull (*src)[PADU], int r0, int bc,
                                      ull (&aR)[8], ull (&aZ)[8], ull (&aN)[8]) {
#pragma unroll
    for (int l = 0; l < 4; ++l) {
        const ull* row = &src[r0 + l][bc];
        ulonglong2 p0 = *(const ulonglong2*)(row);
        ulonglong2 p1 = *(const ulonglong2*)(row + 2);
        ulonglong2 p2 = *(const ulonglong2*)(row + 4);
        ulonglong2 p3 = *(const ulonglong2*)(row + 6);
        ull hv[8] = {p0.x, p0.y, p1.x, p1.y, p2.x, p2.y, p3.x, p3.y};
#pragma unroll
        for (int b = 0; b < 8; ++b) {
            aR[b] = fma2(hv[b], w[l * 3 + 0], aR[b]);
            aZ[b] = fma2(hv[b], w[l * 3 + 1], aZ[b]);
            aN[b] = fma2(hv[b], w[l * 3 + 2], aN[b]);
        }
    }
}

// ---- K7: decoder scan -----------------------------------------------------
// 128 CTAs = 64 p x 2 b-halves (16 b).  256 threads = 2 bg (8 b) x 128 jg (2 j).
// h and x live in smem as pre-duplicated f32x2 -> zero broadcast MOVs in the
// inner loop.  Weights double-buffered in registers (4-layer blocks, 384-cyc
// prefetch distance >> 262-cyc L2 latency).
__global__ __launch_bounds__(256, 1) void dec_kernel(
    const float* __restrict__ bih_d, const float* __restrict__ bhh_d,
    const float* __restrict__ Wlin, const float* __restrict__ blin,
    float* __restrict__ out) {
    __shared__ ull h_d[HH][PADU];   // 36.9 KB, duplicated h
    __shared__ ull x_d[PP][PADU];   //  9.2 KB, duplicated x
    __shared__ float red_s[8][8];

    const int tid = threadIdx.x;
    const int p  = blockIdx.x >> 1;
    const int b0 = (blockIdx.x & 1) * 16;
    const int bg = tid >> 7;          // 0..1
    const int jg = tid & 127;         // 0..127
    const int j0 = jg * 2;
    const int bc = bg * 8;
    const int lane = tid & 31, warp = tid >> 5;

    const float* WtH = g_Wt_hh + (size_t)p * HH * K3H + j0;
    const float* WtI = g_Wt_ih + (size_t)p * PP * K3H + j0;

    for (int idx = tid; idx < HH * 16; idx += 256) {
        int bb = idx & 15, j = idx >> 4;
        h_d[j][bb] = bcast2(g_z[(b0 + bb) * HH + j]);
    }
    const float bR0  = bih_d[p * K3H + j0]          + bhh_d[p * K3H + j0];
    const float bR1  = bih_d[p * K3H + j0 + 1]      + bhh_d[p * K3H + j0 + 1];
    const float bZ0  = bih_d[p * K3H + HH + j0]     + bhh_d[p * K3H + HH + j0];
    const float bZ1  = bih_d[p * K3H + HH + j0 + 1] + bhh_d[p * K3H + HH + j0 + 1];
    const float bNx0 = bih_d[p * K3H + 2 * HH + j0];
    const float bNx1 = bih_d[p * K3H + 2 * HH + j0 + 1];
    const float bNh0 = bhh_d[p * K3H + 2 * HH + j0];
    const float bNh1 = bhh_d[p * K3H + 2 * HH + j0 + 1];
    const float blin_p = blin[p];
    const float wl0 = Wlin[p * HH + j0];
    const float wl1 = Wlin[p * HH + j0 + 1];

#pragma unroll 1
    for (int l = 0; l < LD; ++l) {
        __syncthreads();   // prev-step h_d writes + red_s reuse
        {   // stage x (duplicated) for this step
            int i = tid >> 2, q = tid & 3;
            float4 v = *(const float4*)&g_Xt[l * (PP * BB) + i * BB + b0 + q * 4];
            ulonglong2 d0 = make_ulonglong2(bcast2(v.x), bcast2(v.y));
            ulonglong2 d1 = make_ulonglong2(bcast2(v.z), bcast2(v.w));
            *(ulonglong2*)&x_d[i][q * 4]     = d0;
            *(ulonglong2*)&x_d[i][q * 4 + 2] = d1;
        }
        __syncthreads();

        ull aR[8], aZ[8], aNx[8], aNh[8];
#pragma unroll
        for (int b = 0; b < 8; ++b) { aR[b] = 0; aZ[b] = 0; aNx[b] = 0; aNh[b] = 0; }

        ull wa[12], wb[12];
        // ---- input projection: 64 i-layers, 16 blocks, double buffered ----
        loadW(wa, WtI);
#pragma unroll 1
        for (int ib = 0; ib < 16; ib += 2) {
            loadW(wb, WtI + (ib + 1) * (4 * K3H));
            comp4(wa, x_d, ib * 4, bc, aR, aZ, aNx);
            loadW(wa, WtI + (ib + 2) * (4 * K3H));   // last iter reads pad: harmless
            comp4(wb, x_d, ib * 4 + 4, bc, aR, aZ, aNx);
        }
        // ---- recurrent: 256 h-layers, 64 blocks, double buffered ----------
        loadW(wa, WtH);
#pragma unroll 1
        for (int hb = 0; hb < 64; hb += 2) {
            loadW(wb, WtH + (hb + 1) * (4 * K3H));
            comp4(wa, h_d, hb * 4, bc, aR, aZ, aNh);
            loadW(wa, WtH + (hb + 2) * (4 * K3H));   // last iter reads pad: harmless
            comp4(wb, h_d, hb * 4 + 4, bc, aR, aZ, aNh);
        }
        __syncthreads();   // all GEMM reads of h_d complete

        // ---- gate epilogue + h update + linear-head partials --------------
        float h0v[8], h1v[8];
#pragma unroll
        for (int b = 0; b < 8; ++b) {
            float lo, hi;
            unpack2(h_d[j0][bc + b], lo, hi);     (void)hi;
            h0v[b] = lo;
            unpack2(h_d[j0 + 1][bc + b], lo, hi); (void)hi;
            h1v[b] = lo;
        }

        float hn0[8], hn1[8], part[8];
#pragma unroll
        for (int b = 0; b < 8; ++b) {
            float r0v, r1v, z0v, z1v, nx0, nx1, nh0, nh1;
            unpack2(aR[b], r0v, r1v);
            unpack2(aZ[b], z0v, z1v);
            unpack2(aNx[b], nx0, nx1);
            unpack2(aNh[b], nh0, nh1);
            float rg0 = sigf(r0v + bR0);
            float rg1 = sigf(r1v + bR1);
            float zg0 = sigf(z0v + bZ0);
            float zg1 = sigf(z1v + bZ1);
            float n0 = tfast(nx0 + bNx0 + rg0 * (nh0 + bNh0));
            float n1 = tfast(nx1 + bNx1 + rg1 * (nh1 + bNh1));
            float a0 = n0 + zg0 * (h0v[b] - n0);
            float a1 = n1 + zg1 * (h1v[b] - n1);
            hn0[b] = a0; hn1[b] = a1;
            part[b] = a0 * wl0 + a1 * wl1;
        }
        // write duplicated new h
#pragma unroll
        for (int q = 0; q < 4; ++q) {
            *(ulonglong2*)&h_d[j0][bc + q * 2] =
                make_ulonglong2(bcast2(hn0[q * 2]), bcast2(hn0[q * 2 + 1]));
            *(ulonglong2*)&h_d[j0 + 1][bc + q * 2] =
                make_ulonglong2(bcast2(hn1[q * 2]), bcast2(hn1[q * 2 + 1]));
        }

#pragma unroll
        for (int off = 16; off; off >>= 1)
#pragma unroll
            for (int b = 0; b < 8; ++b)
                part[b] += __shfl_down_sync(0xffffffffu, part[b], off);
        if (lane == 0) {
#pragma unroll
            for (int b = 0; b < 8; ++b) red_s[warp][b] = part[b];
        }
        __syncthreads();
        if (tid < 16) {
            int bgq = tid >> 3, ib = tid & 7;
            float s = red_s[bgq * 4][ib] + red_s[bgq * 4 + 1][ib] +
                      red_s[bgq * 4 + 2][ib] + red_s[bgq * 4 + 3][ib] + blin_p;
            out[(p * BB + b0 + bgq * 8 + ib) * LD + l] = s;
        }
    }
}

// ---------------------------------------------------------------------------
extern "C" void kernel_launch(void* const* d_in, const int* in_sizes, int n_in,
                              void* d_out, int out_size) {
    const float* X     = (const float*)d_in[0];
    const float* eps   = (const float*)d_in[1];
    // d_in[2] = connection (all-ones -> gather identity; unused)
    const float* Wih_e = (const float*)d_in[3];
    const float* Whh_e = (const float*)d_in[4];
    const float* bih_e = (const float*)d_in[5];
    const float* bhh_e = (const float*)d_in[6];
    const float* Wmu   = (const float*)d_in[7];
    const float* bmu   = (const float*)d_in[8];
    const float* Wstd  = (const float*)d_in[9];
    const float* bstd  = (const float*)d_in[10];
    const float* Wih_d = (const float*)d_in[11];
    const float* Whh_d = (const float*)d_in[12];
    const float* bih_d = (const float*)d_in[13];
    const float* bhh_d = (const float*)d_in[14];
    const float* Wlin  = (const float*)d_in[15];
    const float* blin  = (const float*)d_in[16];
    float* out = (float*)d_out;

    transpose_hh_kernel<<<dim3(HH / 32, K3H / 32, PP), dim3(32, 8)>>>(Whh_d);
    transpose_ih_kernel<<<dim3(PP / 32, K3H / 32, PP), dim3(32, 8)>>>(Wih_d);
    build_xt_kernel<<<(LD * PP * BB + 255) / 256, 256>>>(X);
    xpe_kernel<<<dim3(BB, LE), 256>>>(X, Wih_e, bih_e);
    enc_kernel<<<BB, 256>>>(Whh_e, bhh_e);
    muz_kernel<<<BB, 256>>>(Wmu, bmu, Wstd, bstd, eps, out);
    dec_kernel<<<128, 256>>>(bih_d, bhh_d, Wlin, blin, out);
}

// round 6
// speedup vs baseline: 1.0557x; 1.0557x over previous
#include <cuda_runtime.h>
#include <cstdint>

typedef unsigned long long ull;

#define PP   64
#define HH   256
#define BB   32
#define TT   128
#define LE   10
#define LD   118
#define K3H  768   // 3*H
#define PADC 20    // padded smem row width (16 data cols + 4 pad)

#define PRED_ELEMS (PP * BB * LD)
#define MU_OFF     PRED_ELEMS
#define LV_OFF     (PRED_ELEMS + BB * HH)

// ---- scratch (static device allocations) ----------------------------------
// Weight layout: per (p, row) a 128-wide array over jg (j-pairs).
//   rz[o] = { pack2(W_R[j0],W_R[j0+1]), pack2(W_Z[j0],W_Z[j0+1]) }  (16B)
//   n [o] =   pack2(W_N[j0],W_N[j0+1])                              (8B)
// +512 pad entries: prefetch reads one 4-row block past the end.
__device__ ulonglong2 g_Whh_rz[PP * HH * 128 + 512];
__device__ ull        g_Whh_n [PP * HH * 128 + 512];
__device__ ulonglong2 g_Wih_rz[PP * PP * 128 + 512];
__device__ ull        g_Wih_n [PP * PP * 128 + 512];
__device__ float g_Xt[LD * PP * BB];       // [l][i][b]
__device__ float g_xpe[LE * BB * K3H];     // [l][b][k]
__device__ float g_hT[BB * HH];
__device__ float g_z[BB * HH];

// ---- helpers --------------------------------------------------------------
__device__ __forceinline__ ull fma2(ull a, ull b, ull c) {
    ull d;
    asm("fma.rn.f32x2 %0, %1, %2, %3;" : "=l"(d) : "l"(a), "l"(b), "l"(c));
    return d;
}
__device__ __forceinline__ ull bcast2(float x) {
    ull d;
    asm("mov.b64 %0, {%1, %1};" : "=l"(d) : "f"(x));
    return d;
}
__device__ __forceinline__ ull pack2(float lo, float hi) {
    ull d;
    asm("mov.b64 %0, {%1, %2};" : "=l"(d) : "f"(lo), "f"(hi));
    return d;
}
__device__ __forceinline__ void unpack2(ull v, float& x, float& y) {
    asm("mov.b64 {%0, %1}, %2;" : "=f"(x), "=f"(y) : "l"(v));
}
__device__ __forceinline__ float sigf(float x) {
    return __fdividef(1.0f, 1.0f + __expf(-x));
}
__device__ __forceinline__ float tfast(float x) {
    float e = __expf(2.0f * x);
    return 1.0f - __fdividef(2.0f, e + 1.0f);
}

// ---- weight packing: in[p][gate*256+j][c] -> rz/n [(p*C+c)*128 + jg] ------
__device__ __forceinline__ void pack_body(const float* __restrict__ in,
                                          ulonglong2* __restrict__ out_rz,
                                          ull* __restrict__ out_n, int C) {
    __shared__ float tR[32][33], tZ[32][33], tN[32][33];
    int p = blockIdx.x, ct = blockIdx.y, jt = blockIdx.z;
    int tx = threadIdx.x, ty = threadIdx.y;   // 32 x 8
    const float* base = in + (size_t)p * K3H * C;
    int c0 = ct * 32, j0t = jt * 32;
#pragma unroll
    for (int dy = 0; dy < 32; dy += 8) {
        tR[ty + dy][tx] = base[(0 * HH + j0t + ty + dy) * C + c0 + tx];
        tZ[ty + dy][tx] = base[(1 * HH + j0t + ty + dy) * C + c0 + tx];
        tN[ty + dy][tx] = base[(2 * HH + j0t + ty + dy) * C + c0 + tx];
    }
    __syncthreads();
    int jgl = tx & 15;
    int half = tx >> 4;
#pragma unroll
    for (int pass = 0; pass < 2; ++pass) {
        int cl = pass * 16 + ty * 2 + half;
        int c = c0 + cl;
        int jg = jt * 16 + jgl;
        size_t o = ((size_t)p * C + c) * 128 + jg;
        out_rz[o] = make_ulonglong2(pack2(tR[jgl * 2][cl], tR[jgl * 2 + 1][cl]),
                                    pack2(tZ[jgl * 2][cl], tZ[jgl * 2 + 1][cl]));
        out_n[o] = pack2(tN[jgl * 2][cl], tN[jgl * 2 + 1][cl]);
    }
}
__global__ void pack_hh_kernel(const float* __restrict__ in) {
    pack_body(in, g_Whh_rz, g_Whh_n, HH);
}
__global__ void pack_ih_kernel(const float* __restrict__ in) {
    pack_body(in, g_Wih_rz, g_Wih_n, PP);
}

// ---- K3: Xt[l][i][b] = (l==0 ? 0 : X[b][l+9][i]) --------------------------
__global__ void build_xt_kernel(const float* __restrict__ X) {
    int idx = blockIdx.x * blockDim.x + threadIdx.x;
    if (idx >= LD * PP * BB) return;
    int b = idx & 31;
    int r = idx >> 5;
    int i = r & 63;
    int l = r >> 6;
    g_Xt[idx] = (l == 0) ? 0.0f : X[b * (TT * PP) + (l + 9) * PP + i];
}

// ---- K4: encoder input projection -----------------------------------------
__global__ void xpe_kernel(const float* __restrict__ X,
                           const float* __restrict__ Wih_e,
                           const float* __restrict__ bih_e) {
    __shared__ float xr[PP];
    int b = blockIdx.x, l = blockIdx.y;
    int tid = threadIdx.x;  // 256
    if (tid < PP) xr[tid] = X[b * (TT * PP) + l * PP + tid];
    __syncthreads();
#pragma unroll
    for (int g = 0; g < 3; ++g) {
        int k = g * HH + tid;
        float a = bih_e[k];
        const float* w = Wih_e + k * PP;
#pragma unroll
        for (int i = 0; i < PP; i += 4) {
            float4 wv = *(const float4*)(w + i);
            a += wv.x * xr[i] + wv.y * xr[i + 1] + wv.z * xr[i + 2] + wv.w * xr[i + 3];
        }
        g_xpe[(l * BB + b) * K3H + k] = a;
    }
}

// ---- K5: encoder GRU scan -------------------------------------------------
__global__ void enc_kernel(const float* __restrict__ Whh_e,
                           const float* __restrict__ bhh_e) {
    __shared__ float hs[HH];
    int b = blockIdx.x, j = threadIdx.x;
    hs[j] = 0.0f;
    float bR = bhh_e[j], bZ = bhh_e[HH + j], bN = bhh_e[2 * HH + j];
    const float* wR = Whh_e + j * HH;
    const float* wZ = Whh_e + (HH + j) * HH;
    const float* wN = Whh_e + (2 * HH + j) * HH;
    __syncthreads();
    for (int l = 0; l < LE; ++l) {
        float aR = 0.f, aZ = 0.f, aN = 0.f;
#pragma unroll 8
        for (int h = 0; h < HH; h += 4) {
            float4 hv = *(const float4*)&hs[h];
            float4 r4 = *(const float4*)(wR + h);
            float4 z4 = *(const float4*)(wZ + h);
            float4 n4 = *(const float4*)(wN + h);
            aR += r4.x * hv.x + r4.y * hv.y + r4.z * hv.z + r4.w * hv.w;
            aZ += z4.x * hv.x + z4.y * hv.y + z4.z * hv.z + z4.w * hv.w;
            aN += n4.x * hv.x + n4.y * hv.y + n4.z * hv.z + n4.w * hv.w;
        }
        const float* xp = g_xpe + (l * BB + b) * K3H;
        float r = sigf(xp[j] + aR + bR);
        float z = sigf(xp[HH + j] + aZ + bZ);
        float n = tfast(xp[2 * HH + j] + r * (aN + bN));
        float hold = hs[j];
        __syncthreads();
        hs[j] = (1.0f - z) * n + z * hold;
        __syncthreads();
    }
    g_hT[b * HH + j] = hs[j];
}

// ---- K6: mu / log_var / z -------------------------------------------------
__global__ void muz_kernel(const float* __restrict__ Wmu,
                           const float* __restrict__ bmu,
                           const float* __restrict__ Wstd,
                           const float* __restrict__ bstd,
                           const float* __restrict__ eps,
                           float* __restrict__ out) {
    __shared__ float hs[HH];
    int b = blockIdx.x, j = threadIdx.x;
    hs[j] = g_hT[b * HH + j];
    __syncthreads();
    float am = bmu[j], as = bstd[j];
    const float* wm = Wmu + j * HH;
    const float* ws = Wstd + j * HH;
#pragma unroll 8
    for (int h = 0; h < HH; h += 4) {
        float4 hv = *(const float4*)&hs[h];
        float4 m4 = *(const float4*)(wm + h);
        float4 s4 = *(const float4*)(ws + h);
        am += m4.x * hv.x + m4.y * hv.y + m4.z * hv.z + m4.w * hv.w;
        as += s4.x * hv.x + s4.y * hv.y + s4.z * hv.z + s4.w * hv.w;
    }
    out[MU_OFF + b * HH + j] = am;
    out[LV_OFF + b * HH + j] = as;
    g_z[b * HH + j] = am + expf(0.5f * as) * eps[b * HH + j];
}

// ---- decoder inner-loop building blocks -----------------------------------
// Base pointers already include +jg; row stride = 128 entries.
__device__ __forceinline__ void loadW4(ulonglong2 (&rz)[4], ull (&n)[4],
                                       const ulonglong2* rzb, const ull* nb,
                                       int row0) {
#pragma unroll
    for (int l = 0; l < 4; ++l) {
        rz[l] = rzb[(size_t)(row0 + l) * 128];
        n[l]  = nb[(size_t)(row0 + l) * 128];
    }
}

__device__ __forceinline__ void comp4(const ulonglong2 (&rz)[4], const ull (&n)[4],
                                      const float (*src)[PADC], int r0, int bc,
                                      ull (&aR)[8], ull (&aZ)[8], ull (&aN)[8]) {
#pragma unroll
    for (int l = 0; l < 4; ++l) {
        float4 ha = *(const float4*)&src[r0 + l][bc];
        float4 hb = *(const float4*)&src[r0 + l][bc + 4];
        float hv[8] = {ha.x, ha.y, ha.z, ha.w, hb.x, hb.y, hb.z, hb.w};
        ull wR = rz[l].x, wZ = rz[l].y, wN = n[l];
#pragma unroll
        for (int b = 0; b < 8; ++b) {
            ull x2 = bcast2(hv[b]);
            aR[b] = fma2(x2, wR, aR[b]);
            aZ[b] = fma2(x2, wZ, aZ[b]);
            aN[b] = fma2(x2, wN, aN[b]);
        }
    }
}

// ---- K7: decoder scan -----------------------------------------------------
// 128 CTAs = 64 p x 2 b-halves (16 b).  256 threads = 2 bg (8 b) x 128 jg (2 j).
// 2 barriers per step: x double-buffered via register prefetch; output store
// pipelined one step behind through double-buffered red_s.
__global__ __launch_bounds__(256, 1) void dec_kernel(
    const float* __restrict__ bih_d, const float* __restrict__ bhh_d,
    const float* __restrict__ Wlin, const float* __restrict__ blin,
    float* __restrict__ out) {
    __shared__ float h_s[HH][PADC];
    __shared__ float x_s[2][PP][PADC];
    __shared__ float red_s[2][8][8];

    const int tid = threadIdx.x;
    const int p  = blockIdx.x >> 1;
    const int b0 = (blockIdx.x & 1) * 16;
    const int bg = tid >> 7;          // 0..1
    const int jg = tid & 127;         // 0..127
    const int j0 = jg * 2;
    const int bc = bg * 8;
    const int lane = tid & 31, warp = tid >> 5;

    const ulonglong2* rzH = g_Whh_rz + (size_t)p * HH * 128 + jg;
    const ull*        nH  = g_Whh_n  + (size_t)p * HH * 128 + jg;
    const ulonglong2* rzI = g_Wih_rz + (size_t)p * PP * 128 + jg;
    const ull*        nI  = g_Wih_n  + (size_t)p * PP * 128 + jg;

    for (int idx = tid; idx < HH * 16; idx += 256) {
        int bb = idx & 15, j = idx >> 4;
        h_s[j][bb] = g_z[(b0 + bb) * HH + j];
    }
    const float bR0  = bih_d[p * K3H + j0]          + bhh_d[p * K3H + j0];
    const float bR1  = bih_d[p * K3H + j0 + 1]      + bhh_d[p * K3H + j0 + 1];
    const float bZ0  = bih_d[p * K3H + HH + j0]     + bhh_d[p * K3H + HH + j0];
    const float bZ1  = bih_d[p * K3H + HH + j0 + 1] + bhh_d[p * K3H + HH + j0 + 1];
    const float bNx0 = bih_d[p * K3H + 2 * HH + j0];
    const float bNx1 = bih_d[p * K3H + 2 * HH + j0 + 1];
    const float bNh0 = bhh_d[p * K3H + 2 * HH + j0];
    const float bNh1 = bhh_d[p * K3H + 2 * HH + j0 + 1];
    const float blin_p = blin[p];
    const float wl0 = Wlin[p * HH + j0];
    const float wl1 = Wlin[p * HH + j0 + 1];

    // stage x(0); prefetch x(1) into registers
    const int xi = tid >> 2, xq = tid & 3;
    *(float4*)&x_s[0][xi][xq * 4] =
        *(const float4*)&g_Xt[0 * (PP * BB) + xi * BB + b0 + xq * 4];
    float4 xreg = *(const float4*)&g_Xt[1 * (PP * BB) + xi * BB + b0 + xq * 4];
    __syncthreads();   // h_s(0), x_s[0] ready

#pragma unroll 1
    for (int l = 0; l < LD; ++l) {
        const int cur = l & 1;
        ull aR[8], aZ[8], aNx[8], aNh[8];
#pragma unroll
        for (int b = 0; b < 8; ++b) { aR[b] = 0; aZ[b] = 0; aNx[b] = 0; aNh[b] = 0; }

        ulonglong2 rza[4], rzb[4];
        ull na[4], nb[4];
        const float (*xs)[PADC] = x_s[cur];

        // ---- input projection: 64 i-rows, double buffered -----------------
        loadW4(rza, na, rzI, nI, 0);
#pragma unroll 1
        for (int ib = 0; ib < 16; ib += 2) {
            loadW4(rzb, nb, rzI, nI, (ib + 1) * 4);
            comp4(rza, na, xs, ib * 4, bc, aR, aZ, aNx);
            loadW4(rza, na, rzI, nI, (ib + 2) * 4);   // last iter: pad, harmless
            comp4(rzb, nb, xs, ib * 4 + 4, bc, aR, aZ, aNx);
        }
        // ---- recurrent: 256 h-rows, double buffered ------------------------
        loadW4(rza, na, rzH, nH, 0);
#pragma unroll 1
        for (int hb = 0; hb < 64; hb += 2) {
            loadW4(rzb, nb, rzH, nH, (hb + 1) * 4);
            comp4(rza, na, h_s, hb * 4, bc, aR, aZ, aNh);
            loadW4(rza, na, rzH, nH, (hb + 2) * 4);   // last iter: pad, harmless
            comp4(rzb, nb, h_s, hb * 4 + 4, bc, aR, aZ, aNh);
        }

        // ---- pipelined output store for step l-1 ---------------------------
        if (tid < 16 && l) {
            int bgq = tid >> 3, ib2 = tid & 7;
            const float (*rs)[8] = red_s[(l + 1) & 1];   // == (l-1)&1
            float s = rs[bgq * 4][ib2] + rs[bgq * 4 + 1][ib2] +
                      rs[bgq * 4 + 2][ib2] + rs[bgq * 4 + 3][ib2] + blin_p;
            out[(p * BB + b0 + bgq * 8 + ib2) * LD + (l - 1)] = s;
        }
        __syncthreads();   // all GEMM reads of h_s / x_s[cur] complete

        // ---- gate epilogue + h update + linear-head partials ---------------
        float4 o00 = *(const float4*)&h_s[j0][bc];
        float4 o01 = *(const float4*)&h_s[j0][bc + 4];
        float4 o10 = *(const float4*)&h_s[j0 + 1][bc];
        float4 o11 = *(const float4*)&h_s[j0 + 1][bc + 4];
        float h0v[8] = {o00.x, o00.y, o00.z, o00.w, o01.x, o01.y, o01.z, o01.w};
        float h1v[8] = {o10.x, o10.y, o10.z, o10.w, o11.x, o11.y, o11.z, o11.w};

        float hn0[8], hn1[8], part[8];
#pragma unroll
        for (int b = 0; b < 8; ++b) {
            float r0v, r1v, z0v, z1v, nx0, nx1, nh0, nh1;
            unpack2(aR[b], r0v, r1v);
            unpack2(aZ[b], z0v, z1v);
            unpack2(aNx[b], nx0, nx1);
            unpack2(aNh[b], nh0, nh1);
            float rg0 = sigf(r0v + bR0);
            float rg1 = sigf(r1v + bR1);
            float zg0 = sigf(z0v + bZ0);
            float zg1 = sigf(z1v + bZ1);
            float n0 = tfast(nx0 + bNx0 + rg0 * (nh0 + bNh0));
            float n1 = tfast(nx1 + bNx1 + rg1 * (nh1 + bNh1));
            float a0 = n0 + zg0 * (h0v[b] - n0);
            float a1 = n1 + zg1 * (h1v[b] - n1);
            hn0[b] = a0; hn1[b] = a1;
            part[b] = a0 * wl0 + a1 * wl1;
        }
        *(float4*)&h_s[j0][bc]         = make_float4(hn0[0], hn0[1], hn0[2], hn0[3]);
        *(float4*)&h_s[j0][bc + 4]     = make_float4(hn0[4], hn0[5], hn0[6], hn0[7]);
        *(float4*)&h_s[j0 + 1][bc]     = make_float4(hn1[0], hn1[1], hn1[2], hn1[3]);
        *(float4*)&h_s[j0 + 1][bc + 4] = make_float4(hn1[4], hn1[5], hn1[6], hn1[7]);

        // stage x for step l+1 from registers; prefetch x(l+2)
        *(float4*)&x_s[cur ^ 1][xi][xq * 4] = xreg;
        if (l + 2 < LD)
            xreg = *(const float4*)&g_Xt[(l + 2) * (PP * BB) + xi * BB + b0 + xq * 4];

#pragma unroll
        for (int off = 16; off; off >>= 1)
#pragma unroll
            for (int b = 0; b < 8; ++b)
                part[b] += __shfl_down_sync(0xffffffffu, part[b], off);
        if (lane == 0) {
#pragma unroll
            for (int b = 0; b < 8; ++b) red_s[cur][warp][b] = part[b];
        }
        __syncthreads();   // h_s(l+1), x_s[cur^1], red_s[cur] ready
    }
    // final output store (step LD-1)
    if (tid < 16) {
        int bgq = tid >> 3, ib2 = tid & 7;
        const float (*rs)[8] = red_s[(LD - 1) & 1];
        float s = rs[bgq * 4][ib2] + rs[bgq * 4 + 1][ib2] +
                  rs[bgq * 4 + 2][ib2] + rs[bgq * 4 + 3][ib2] + blin_p;
        out[(p * BB + b0 + bgq * 8 + ib2) * LD + (LD - 1)] = s;
    }
}

// ---------------------------------------------------------------------------
extern "C" void kernel_launch(void* const* d_in, const int* in_sizes, int n_in,
                              void* d_out, int out_size) {
    const float* X     = (const float*)d_in[0];
    const float* eps   = (const float*)d_in[1];
    // d_in[2] = connection (all-ones -> gather identity; unused)
    const float* Wih_e = (const float*)d_in[3];
    const float* Whh_e = (const float*)d_in[4];
    const float* bih_e = (const float*)d_in[5];
    const float* bhh_e = (const float*)d_in[6];
    const float* Wmu   = (const float*)d_in[7];
    const float* bmu   = (const float*)d_in[8];
    const float* Wstd  = (const float*)d_in[9];
    const float* bstd  = (const float*)d_in[10];
    const float* Wih_d = (const float*)d_in[11];
    const float* Whh_d = (const float*)d_in[12];
    const float* bih_d = (const float*)d_in[13];
    const float* bhh_d = (const float*)d_in[14];
    const float* Wlin  = (const float*)d_in[15];
    const float* blin  = (const float*)d_in[16];
    float* out = (float*)d_out;

    pack_hh_kernel<<<dim3(PP, HH / 32, 8), dim3(32, 8)>>>(Whh_d);
    pack_ih_kernel<<<dim3(PP, PP / 32, 8), dim3(32, 8)>>>(Wih_d);
    build_xt_kernel<<<(LD * PP * BB + 255) / 256, 256>>>(X);
    xpe_kernel<<<dim3(BB, LE), 256>>>(X, Wih_e, bih_e);
    enc_kernel<<<BB, 256>>>(Whh_e, bhh_e);
    muz_kernel<<<BB, 256>>>(Wmu, bmu, Wstd, bstd, eps, out);
    dec_kernel<<<128, 256>>>(bih_d, bhh_d, Wlin, blin, out);
}

// round 7
// speedup vs baseline: 1.0577x; 1.0019x over previous
#include <cuda_runtime.h>
#include <cstdint>

typedef unsigned long long ull;

#define PP   64
#define HH   256
#define BB   32
#define TT   128
#define LE   10
#define LD   118
#define K3H  768   // 3*H
#define PADC 20    // padded smem row width (16 data cols + 4 pad)

#define PRED_ELEMS (PP * BB * LD)
#define MU_OFF     PRED_ELEMS
#define LV_OFF     (PRED_ELEMS + BB * HH)

// ---- scratch (static device allocations) ----------------------------------
// Weight layout: per (p, row) a 128-wide array over jg (j-pairs).
//   rz[o] = { pack2(W_R[j0],W_R[j0+1]), pack2(W_Z[j0],W_Z[j0+1]) }  (16B)
//   n [o] =   pack2(W_N[j0],W_N[j0+1])                              (8B)
// +512 pad entries: prefetch reads one 4-row block past the end.
__device__ ulonglong2 g_Whh_rz[PP * HH * 128 + 512];
__device__ ull        g_Whh_n [PP * HH * 128 + 512];
__device__ ulonglong2 g_Wih_rz[PP * PP * 128 + 512];
__device__ ull        g_Wih_n [PP * PP * 128 + 512];
__device__ float g_Xt[LD * PP * BB];       // [l][i][b]
__device__ float g_xpe[LE * BB * K3H];     // [l][b][k]
__device__ float g_hT[BB * HH];
__device__ float g_z[BB * HH];

// ---- helpers --------------------------------------------------------------
__device__ __forceinline__ ull fma2(ull a, ull b, ull c) {
    ull d;
    asm("fma.rn.f32x2 %0, %1, %2, %3;" : "=l"(d) : "l"(a), "l"(b), "l"(c));
    return d;
}
__device__ __forceinline__ ull bcast2(float x) {
    ull d;
    asm("mov.b64 %0, {%1, %1};" : "=l"(d) : "f"(x));
    return d;
}
__device__ __forceinline__ ull pack2(float lo, float hi) {
    ull d;
    asm("mov.b64 %0, {%1, %2};" : "=l"(d) : "f"(lo), "f"(hi));
    return d;
}
__device__ __forceinline__ void unpack2(ull v, float& x, float& y) {
    asm("mov.b64 {%0, %1}, %2;" : "=f"(x), "=f"(y) : "l"(v));
}
__device__ __forceinline__ float sigf(float x) {
    return __fdividef(1.0f, 1.0f + __expf(-x));
}
__device__ __forceinline__ float tfast(float x) {
    float e = __expf(2.0f * x);
    return 1.0f - __fdividef(2.0f, e + 1.0f);
}

// ---- weight packing: in[p][gate*256+j][c] -> rz/n [(p*C+c)*128 + jg] ------
__device__ __forceinline__ void pack_body(const float* __restrict__ in,
                                          ulonglong2* __restrict__ out_rz,
                                          ull* __restrict__ out_n, int C) {
    __shared__ float tR[32][33], tZ[32][33], tN[32][33];
    int p = blockIdx.x, ct = blockIdx.y, jt = blockIdx.z;
    int tx = threadIdx.x, ty = threadIdx.y;   // 32 x 8
    const float* base = in + (size_t)p * K3H * C;
    int c0 = ct * 32, j0t = jt * 32;
#pragma unroll
    for (int dy = 0; dy < 32; dy += 8) {
        tR[ty + dy][tx] = base[(0 * HH + j0t + ty + dy) * C + c0 + tx];
        tZ[ty + dy][tx] = base[(1 * HH + j0t + ty + dy) * C + c0 + tx];
        tN[ty + dy][tx] = base[(2 * HH + j0t + ty + dy) * C + c0 + tx];
    }
    __syncthreads();
    int jgl = tx & 15;
    int half = tx >> 4;
#pragma unroll
    for (int pass = 0; pass < 2; ++pass) {
        int cl = pass * 16 + ty * 2 + half;
        int c = c0 + cl;
        int jg = jt * 16 + jgl;
        size_t o = ((size_t)p * C + c) * 128 + jg;
        out_rz[o] = make_ulonglong2(pack2(tR[jgl * 2][cl], tR[jgl * 2 + 1][cl]),
                                    pack2(tZ[jgl * 2][cl], tZ[jgl * 2 + 1][cl]));
        out_n[o] = pack2(tN[jgl * 2][cl], tN[jgl * 2 + 1][cl]);
    }
}
__global__ void pack_hh_kernel(const float* __restrict__ in) {
    pack_body(in, g_Whh_rz, g_Whh_n, HH);
}
__global__ void pack_ih_kernel(const float* __restrict__ in) {
    pack_body(in, g_Wih_rz, g_Wih_n, PP);
}

// ---- K3: Xt[l][i][b] = (l==0 ? 0 : X[b][l+9][i]) --------------------------
__global__ void build_xt_kernel(const float* __restrict__ X) {
    int idx = blockIdx.x * blockDim.x + threadIdx.x;
    if (idx >= LD * PP * BB) return;
    int b = idx & 31;
    int r = idx >> 5;
    int i = r & 63;
    int l = r >> 6;
    g_Xt[idx] = (l == 0) ? 0.0f : X[b * (TT * PP) + (l + 9) * PP + i];
}

// ---- K4: encoder input projection -----------------------------------------
__global__ void xpe_kernel(const float* __restrict__ X,
                           const float* __restrict__ Wih_e,
                           const float* __restrict__ bih_e) {
    __shared__ float xr[PP];
    int b = blockIdx.x, l = blockIdx.y;
    int tid = threadIdx.x;  // 256
    if (tid < PP) xr[tid] = X[b * (TT * PP) + l * PP + tid];
    __syncthreads();
#pragma unroll
    for (int g = 0; g < 3; ++g) {
        int k = g * HH + tid;
        float a = bih_e[k];
        const float* w = Wih_e + k * PP;
#pragma unroll
        for (int i = 0; i < PP; i += 4) {
            float4 wv = *(const float4*)(w + i);
            a += wv.x * xr[i] + wv.y * xr[i + 1] + wv.z * xr[i + 2] + wv.w * xr[i + 3];
        }
        g_xpe[(l * BB + b) * K3H + k] = a;
    }
}

// ---- K5: encoder GRU scan -------------------------------------------------
__global__ void enc_kernel(const float* __restrict__ Whh_e,
                           const float* __restrict__ bhh_e) {
    __shared__ float hs[HH];
    int b = blockIdx.x, j = threadIdx.x;
    hs[j] = 0.0f;
    float bR = bhh_e[j], bZ = bhh_e[HH + j], bN = bhh_e[2 * HH + j];
    const float* wR = Whh_e + j * HH;
    const float* wZ = Whh_e + (HH + j) * HH;
    const float* wN = Whh_e + (2 * HH + j) * HH;
    __syncthreads();
    for (int l = 0; l < LE; ++l) {
        float aR = 0.f, aZ = 0.f, aN = 0.f;
#pragma unroll 8
        for (int h = 0; h < HH; h += 4) {
            float4 hv = *(const float4*)&hs[h];
            float4 r4 = *(const float4*)(wR + h);
            float4 z4 = *(const float4*)(wZ + h);
            float4 n4 = *(const float4*)(wN + h);
            aR += r4.x * hv.x + r4.y * hv.y + r4.z * hv.z + r4.w * hv.w;
            aZ += z4.x * hv.x + z4.y * hv.y + z4.z * hv.z + z4.w * hv.w;
            aN += n4.x * hv.x + n4.y * hv.y + n4.z * hv.z + n4.w * hv.w;
        }
        const float* xp = g_xpe + (l * BB + b) * K3H;
        float r = sigf(xp[j] + aR + bR);
        float z = sigf(xp[HH + j] + aZ + bZ);
        float n = tfast(xp[2 * HH + j] + r * (aN + bN));
        float hold = hs[j];
        __syncthreads();
        hs[j] = (1.0f - z) * n + z * hold;
        __syncthreads();
    }
    g_hT[b * HH + j] = hs[j];
}

// ---- K6: mu / log_var / z -------------------------------------------------
__global__ void muz_kernel(const float* __restrict__ Wmu,
                           const float* __restrict__ bmu,
                           const float* __restrict__ Wstd,
                           const float* __restrict__ bstd,
                           const float* __restrict__ eps,
                           float* __restrict__ out) {
    __shared__ float hs[HH];
    int b = blockIdx.x, j = threadIdx.x;
    hs[j] = g_hT[b * HH + j];
    __syncthreads();
    float am = bmu[j], as = bstd[j];
    const float* wm = Wmu + j * HH;
    const float* ws = Wstd + j * HH;
#pragma unroll 8
    for (int h = 0; h < HH; h += 4) {
        float4 hv = *(const float4*)&hs[h];
        float4 m4 = *(const float4*)(wm + h);
        float4 s4 = *(const float4*)(ws + h);
        am += m4.x * hv.x + m4.y * hv.y + m4.z * hv.z + m4.w * hv.w;
        as += s4.x * hv.x + s4.y * hv.y + s4.z * hv.z + s4.w * hv.w;
    }
    out[MU_OFF + b * HH + j] = am;
    out[LV_OFF + b * HH + j] = as;
    g_z[b * HH + j] = am + expf(0.5f * as) * eps[b * HH + j];
}

// ---- decoder inner-loop building blocks -----------------------------------
// Base pointers already include +jg; row stride = 128 entries.
__device__ __forceinline__ void loadW4(ulonglong2 (&rz)[4], ull (&n)[4],
                                       const ulonglong2* rzb, const ull* nb,
                                       int row0) {
#pragma unroll
    for (int l = 0; l < 4; ++l) {
        rz[l] = rzb[(size_t)(row0 + l) * 128];
        n[l]  = nb[(size_t)(row0 + l) * 128];
    }
}

__device__ __forceinline__ void comp4(const ulonglong2 (&rz)[4], const ull (&n)[4],
                                      const float (*src)[PADC], int r0, int bc,
                                      ull (&aR)[8], ull (&aZ)[8], ull (&aN)[8]) {
#pragma unroll
    for (int l = 0; l < 4; ++l) {
        float4 ha = *(const float4*)&src[r0 + l][bc];
        float4 hb = *(const float4*)&src[r0 + l][bc + 4];
        float hv[8] = {ha.x, ha.y, ha.z, ha.w, hb.x, hb.y, hb.z, hb.w};
        ull wR = rz[l].x, wZ = rz[l].y, wN = n[l];
#pragma unroll
        for (int b = 0; b < 8; ++b) {
            ull x2 = bcast2(hv[b]);
            aR[b] = fma2(x2, wR, aR[b]);
            aZ[b] = fma2(x2, wZ, aZ[b]);
            aN[b] = fma2(x2, wN, aN[b]);
        }
    }
}

// ---- K7: decoder scan -----------------------------------------------------
// 128 CTAs = 64 p x 2 b-halves (16 b).  256 threads = 2 bg (8 b) x 128 jg (2 j).
// 2 barriers per step: x double-buffered via register prefetch; output store
// pipelined one step behind through double-buffered red_s.
__global__ __launch_bounds__(256, 1) void dec_kernel(
    const float* __restrict__ bih_d, const float* __restrict__ bhh_d,
    const float* __restrict__ Wlin, const float* __restrict__ blin,
    float* __restrict__ out) {
    __shared__ float h_s[HH][PADC];
    __shared__ float x_s[2][PP][PADC];
    __shared__ float red_s[2][8][8];

    const int tid = threadIdx.x;
    const int p  = blockIdx.x >> 1;
    const int b0 = (blockIdx.x & 1) * 16;
    const int bg = tid >> 7;          // 0..1
    const int jg = tid & 127;         // 0..127
    const int j0 = jg * 2;
    const int bc = bg * 8;
    const int lane = tid & 31, warp = tid >> 5;

    const ulonglong2* rzH = g_Whh_rz + (size_t)p * HH * 128 + jg;
    const ull*        nH  = g_Whh_n  + (size_t)p * HH * 128 + jg;
    const ulonglong2* rzI = g_Wih_rz + (size_t)p * PP * 128 + jg;
    const ull*        nI  = g_Wih_n  + (size_t)p * PP * 128 + jg;

    for (int idx = tid; idx < HH * 16; idx += 256) {
        int bb = idx & 15, j = idx >> 4;
        h_s[j][bb] = g_z[(b0 + bb) * HH + j];
    }
    const float bR0  = bih_d[p * K3H + j0]          + bhh_d[p * K3H + j0];
    const float bR1  = bih_d[p * K3H + j0 + 1]      + bhh_d[p * K3H + j0 + 1];
    const float bZ0  = bih_d[p * K3H + HH + j0]     + bhh_d[p * K3H + HH + j0];
    const float bZ1  = bih_d[p * K3H + HH + j0 + 1] + bhh_d[p * K3H + HH + j0 + 1];
    const float bNx0 = bih_d[p * K3H + 2 * HH + j0];
    const float bNx1 = bih_d[p * K3H + 2 * HH + j0 + 1];
    const float bNh0 = bhh_d[p * K3H + 2 * HH + j0];
    const float bNh1 = bhh_d[p * K3H + 2 * HH + j0 + 1];
    const float blin_p = blin[p];
    const float wl0 = Wlin[p * HH + j0];
    const float wl1 = Wlin[p * HH + j0 + 1];

    // stage x(0); prefetch x(1) into registers
    const int xi = tid >> 2, xq = tid & 3;
    *(float4*)&x_s[0][xi][xq * 4] =
        *(const float4*)&g_Xt[0 * (PP * BB) + xi * BB + b0 + xq * 4];
    float4 xreg = *(const float4*)&g_Xt[1 * (PP * BB) + xi * BB + b0 + xq * 4];
    __syncthreads();   // h_s(0), x_s[0] ready

#pragma unroll 1
    for (int l = 0; l < LD; ++l) {
        const int cur = l & 1;
        ull aR[8], aZ[8], aNx[8], aNh[8];
#pragma unroll
        for (int b = 0; b < 8; ++b) { aR[b] = 0; aZ[b] = 0; aNx[b] = 0; aNh[b] = 0; }

        ulonglong2 rza[4], rzb[4];
        ull na[4], nb[4];
        const float (*xs)[PADC] = x_s[cur];

        // ---- input projection: 64 i-rows, double buffered -----------------
        loadW4(rza, na, rzI, nI, 0);
#pragma unroll 1
        for (int ib = 0; ib < 16; ib += 2) {
            loadW4(rzb, nb, rzI, nI, (ib + 1) * 4);
            comp4(rza, na, xs, ib * 4, bc, aR, aZ, aNx);
            loadW4(rza, na, rzI, nI, (ib + 2) * 4);   // last iter: pad, harmless
            comp4(rzb, nb, xs, ib * 4 + 4, bc, aR, aZ, aNx);
        }
        // ---- recurrent: 256 h-rows, double buffered ------------------------
        loadW4(rza, na, rzH, nH, 0);
#pragma unroll 1
        for (int hb = 0; hb < 64; hb += 2) {
            loadW4(rzb, nb, rzH, nH, (hb + 1) * 4);
            comp4(rza, na, h_s, hb * 4, bc, aR, aZ, aNh);
            loadW4(rza, na, rzH, nH, (hb + 2) * 4);   // last iter: pad, harmless
            comp4(rzb, nb, h_s, hb * 4 + 4, bc, aR, aZ, aNh);
        }

        // ---- pipelined output store for step l-1 ---------------------------
        if (tid < 16 && l) {
            int bgq = tid >> 3, ib2 = tid & 7;
            const float (*rs)[8] = red_s[(l + 1) & 1];   // == (l-1)&1
            float s = rs[bgq * 4][ib2] + rs[bgq * 4 + 1][ib2] +
                      rs[bgq * 4 + 2][ib2] + rs[bgq * 4 + 3][ib2] + blin_p;
            out[(p * BB + b0 + bgq * 8 + ib2) * LD + (l - 1)] = s;
        }
        __syncthreads();   // all GEMM reads of h_s / x_s[cur] complete

        // ---- gate epilogue + h update + linear-head partials ---------------
        float4 o00 = *(const float4*)&h_s[j0][bc];
        float4 o01 = *(const float4*)&h_s[j0][bc + 4];
        float4 o10 = *(const float4*)&h_s[j0 + 1][bc];
        float4 o11 = *(const float4*)&h_s[j0 + 1][bc + 4];
        float h0v[8] = {o00.x, o00.y, o00.z, o00.w, o01.x, o01.y, o01.z, o01.w};
        float h1v[8] = {o10.x, o10.y, o10.z, o10.w, o11.x, o11.y, o11.z, o11.w};

        float hn0[8], hn1[8], part[8];
#pragma unroll
        for (int b = 0; b < 8; ++b) {
            float r0v, r1v, z0v, z1v, nx0, nx1, nh0, nh1;
            unpack2(aR[b], r0v, r1v);
            unpack2(aZ[b], z0v, z1v);
            unpack2(aNx[b], nx0, nx1);
            unpack2(aNh[b], nh0, nh1);
            float rg0 = sigf(r0v + bR0);
            float rg1 = sigf(r1v + bR1);
            float zg0 = sigf(z0v + bZ0);
            float zg1 = sigf(z1v + bZ1);
            float n0 = tfast(nx0 + bNx0 + rg0 * (nh0 + bNh0));
            float n1 = tfast(nx1 + bNx1 + rg1 * (nh1 + bNh1));
            float a0 = n0 + zg0 * (h0v[b] - n0);
            float a1 = n1 + zg1 * (h1v[b] - n1);
            hn0[b] = a0; hn1[b] = a1;
            part[b] = a0 * wl0 + a1 * wl1;
        }
        *(float4*)&h_s[j0][bc]         = make_float4(hn0[0], hn0[1], hn0[2], hn0[3]);
        *(float4*)&h_s[j0][bc + 4]     = make_float4(hn0[4], hn0[5], hn0[6], hn0[7]);
        *(float4*)&h_s[j0 + 1][bc]     = make_float4(hn1[0], hn1[1], hn1[2], hn1[3]);
        *(float4*)&h_s[j0 + 1][bc + 4] = make_float4(hn1[4], hn1[5], hn1[6], hn1[7]);

        // stage x for step l+1 from registers; prefetch x(l+2)
        *(float4*)&x_s[cur ^ 1][xi][xq * 4] = xreg;
        if (l + 2 < LD)
            xreg = *(const float4*)&g_Xt[(l + 2) * (PP * BB) + xi * BB + b0 + xq * 4];

#pragma unroll
        for (int off = 16; off; off >>= 1)
#pragma unroll
            for (int b = 0; b < 8; ++b)
                part[b] += __shfl_down_sync(0xffffffffu, part[b], off);
        if (lane == 0) {
#pragma unroll
            for (int b = 0; b < 8; ++b) red_s[cur][warp][b] = part[b];
        }
        __syncthreads();   // h_s(l+1), x_s[cur^1], red_s[cur] ready
    }
    // final output store (step LD-1)
    if (tid < 16) {
        int bgq = tid >> 3, ib2 = tid & 7;
        const float (*rs)[8] = red_s[(LD - 1) & 1];
        float s = rs[bgq * 4][ib2] + rs[bgq * 4 + 1][ib2] +
                  rs[bgq * 4 + 2][ib2] + rs[bgq * 4 + 3][ib2] + blin_p;
        out[(p * BB + b0 + bgq * 8 + ib2) * LD + (LD - 1)] = s;
    }
}

// ---------------------------------------------------------------------------
extern "C" void kernel_launch(void* const* d_in, const int* in_sizes, int n_in,
                              void* d_out, int out_size) {
    const float* X     = (const float*)d_in[0];
    const float* eps   = (const float*)d_in[1];
    // d_in[2] = connection (all-ones -> gather identity; unused)
    const float* Wih_e = (const float*)d_in[3];
    const float* Whh_e = (const float*)d_in[4];
    const float* bih_e = (const float*)d_in[5];
    const float* bhh_e = (const float*)d_in[6];
    const float* Wmu   = (const float*)d_in[7];
    const float* bmu   = (const float*)d_in[8];
    const float* Wstd  = (const float*)d_in[9];
    const float* bstd  = (const float*)d_in[10];
    const float* Wih_d = (const float*)d_in[11];
    const float* Whh_d = (const float*)d_in[12];
    const float* bih_d = (const float*)d_in[13];
    const float* bhh_d = (const float*)d_in[14];
    const float* Wlin  = (const float*)d_in[15];
    const float* blin  = (const float*)d_in[16];
    float* out = (float*)d_out;

    pack_hh_kernel<<<dim3(PP, HH / 32, 8), dim3(32, 8)>>>(Whh_d);
    pack_ih_kernel<<<dim3(PP, PP / 32, 8), dim3(32, 8)>>>(Wih_d);
    build_xt_kernel<<<(LD * PP * BB + 255) / 256, 256>>>(X);
    xpe_kernel<<<dim3(BB, LE), 256>>>(X, Wih_e, bih_e);
    enc_kernel<<<BB, 256>>>(Whh_e, bhh_e);
    muz_kernel<<<BB, 256>>>(Wmu, bmu, Wstd, bstd, eps, out);
    dec_kernel<<<128, 256>>>(bih_d, bhh_d, Wlin, blin, out);
}

// round 9
// speedup vs baseline: 1.9174x; 1.8128x over previous
#include <cuda_runtime.h>
#include <cuda_bf16.h>
#include <cstdint>

#define PP   64
#define HH   256
#define BB   32
#define TT   128
#define LE   10
#define LSTEPS 118
#define K3H  768
#define NCH  20          // k-chunks per step (16 h + 4 x)
#define RING 4
#define CHUNK_BYTES 49152

#define PRED_ELEMS (PP * BB * LSTEPS)
#define MU_OFF     PRED_ELEMS
#define LV_OFF     (PRED_ELEMS + BB * HH)

// ---- smem offsets (bytes) ----------------------------------------------------
#define FULL_OFF   0       // 4 x 8B
#define EMPTY_OFF  32      // 4 x 8B
#define RED_OFF    64      // 8*16 floats = 512B
#define VHI_OFF    1024    // 160*16 u32 = 10240
#define VLO_OFF    11264   // 10240
#define RING_OFF   21504   // 4 x 49152
#define SMEM_TOTAL 218112

// ---- static scratch ------------------------------------------------------------
__device__ __align__(16) unsigned char g_Wpk[(size_t)PP * NCH * CHUNK_BYTES]; // 63MB
__device__ uint32_t g_Xpk[LSTEPS * 2 * 2 * 512];   // [l][bhalf][hi/lo][512 words]
__device__ float g_xpe[LE * BB * K3H];
__device__ float g_hT[BB * HH];
__device__ float g_z[BB * HH];

// ---- helpers ---------------------------------------------------------------------
__device__ __forceinline__ uint32_t s2u(const void* p) {
    uint32_t a;
    asm("{ .reg .u64 t; cvta.to.shared.u64 t, %1; cvt.u32.u64 %0, t; }" : "=r"(a) : "l"(p));
    return a;
}
__device__ __forceinline__ float sigf(float x) { return __fdividef(1.0f, 1.0f + __expf(-x)); }
__device__ __forceinline__ float tfast(float x) {
    float e = __expf(2.0f * x);
    return 1.0f - __fdividef(2.0f, e + 1.0f);
}
__device__ __forceinline__ void mbar_init(uint32_t mb, uint32_t cnt) {
    asm volatile("mbarrier.init.shared.b64 [%0], %1;" :: "r"(mb), "r"(cnt) : "memory");
}
__device__ __forceinline__ void mbar_arrive(uint32_t mb) {
    asm volatile("mbarrier.arrive.shared.b64 _, [%0];" :: "r"(mb) : "memory");
}
__device__ __forceinline__ void mbar_expect(uint32_t mb, uint32_t bytes) {
    asm volatile("mbarrier.arrive.expect_tx.shared.b64 _, [%0], %1;"
                 :: "r"(mb), "r"(bytes) : "memory");
}
__device__ __forceinline__ void mwait(uint32_t mb, uint32_t par) {
    asm volatile(
        "{\n\t.reg .pred P;\n"
        "LW%=:\n\t"
        "mbarrier.try_wait.parity.acquire.cta.shared::cta.b64 P, [%0], %1, 0x989680;\n\t"
        "@!P bra LW%=;\n\t}"
        :: "r"(mb), "r"(par) : "memory");
}
__device__ __forceinline__ void bulk_cp(uint32_t dst, const void* src, uint32_t bytes,
                                        uint32_t mb) {
    asm volatile(
        "cp.async.bulk.shared::cluster.global.mbarrier::complete_tx::bytes [%0], [%1], %2, [%3];"
        :: "r"(dst), "l"(src), "r"(bytes), "r"(mb) : "memory");
}
__device__ __forceinline__ void lm4(uint32_t* r, uint32_t addr) {
    asm volatile("ldmatrix.sync.aligned.m8n8.x4.shared.b16 {%0,%1,%2,%3}, [%4];"
                 : "=r"(r[0]), "=r"(r[1]), "=r"(r[2]), "=r"(r[3]) : "r"(addr));
}
__device__ __forceinline__ void mma16816(float* c, const uint32_t* a,
                                         uint32_t b0, uint32_t b1) {
    asm volatile(
        "mma.sync.aligned.m16n8k16.row.col.f32.bf16.bf16.f32 "
        "{%0,%1,%2,%3}, {%4,%5,%6,%7}, {%8,%9}, {%0,%1,%2,%3};"
        : "+f"(c[0]), "+f"(c[1]), "+f"(c[2]), "+f"(c[3])
        : "r"(a[0]), "r"(a[1]), "r"(a[2]), "r"(a[3]), "r"(b0), "r"(b1));
}
__device__ __forceinline__ uint32_t packbf2(float v0, float v1) {
    __nv_bfloat16 h0 = __float2bfloat16(v0), h1 = __float2bfloat16(v1);
    uint16_t u0 = *(uint16_t*)&h0, u1 = *(uint16_t*)&h1;
    return (uint32_t)u0 | ((uint32_t)u1 << 16);
}

// ---- prepack weights: ldmatrix-ready 16x16 bf16 tiles (hi/lo) ---------------------
// chunk image layout: [wc(8)][mt(2)][gate(3)][hl(2)] x 512B; rows 16 x 32B.
__global__ void packW_kernel(const float* __restrict__ Whh,
                             const float* __restrict__ Wih) {
    int p = blockIdx.x, c = blockIdx.y;
    unsigned char* base = g_Wpk + ((size_t)p * NCH + c) * CHUNK_BYTES;
    for (int idx = threadIdx.x; idx < 768 * 16; idx += 256) {
        int row = idx >> 4, kk = idx & 15;
        int g = row >> 8, j = row & 255;
        float v = (c < 16)
            ? Whh[((size_t)p * K3H + g * 256 + j) * HH + c * 16 + kk]
            : Wih[((size_t)p * K3H + g * 256 + j) * PP + (c - 16) * 16 + kk];
        __nv_bfloat16 hi = __float2bfloat16(v);
        __nv_bfloat16 lo = __float2bfloat16(v - __bfloat162float(hi));
        uint32_t off = (uint32_t)((((j >> 5) * 2 + ((j >> 4) & 1)) * 3 + g) * 2) * 512
                     + (j & 15) * 32 + kk * 2;
        *(__nv_bfloat16*)(base + off) = hi;
        *(__nv_bfloat16*)(base + off + 512) = lo;
    }
}

// ---- prepack x words: [l][bhalf][hi/lo][512] (word = {x[2k],x[2k+1]} for col b) ---
__global__ void packX_kernel(const float* __restrict__ X) {
    int l = blockIdx.x;
    for (int e = threadIdx.x; e < 2048; e += 256) {
        int half = e >> 10, t = (e >> 9) & 1, w = e & 511;
        int k2 = w >> 4, b = w & 15;
        int bglob = half * 16 + b;
        float v0 = 0.f, v1 = 0.f;
        if (l != 0) {
            v0 = X[(size_t)bglob * TT * PP + (l + 9) * PP + 2 * k2];
            v1 = X[(size_t)bglob * TT * PP + (l + 9) * PP + 2 * k2 + 1];
        }
        uint32_t word;
        if (t == 0) {
            word = packbf2(v0, v1);
        } else {
            float h0 = __bfloat162float(__float2bfloat16(v0));
            float h1 = __bfloat162float(__float2bfloat16(v1));
            word = packbf2(v0 - h0, v1 - h1);
        }
        g_Xpk[((l * 2 + half) * 2 + t) * 512 + w] = word;
    }
}

// ---- encoder input projection -------------------------------------------------------
__global__ void xpe_kernel(const float* __restrict__ X,
                           const float* __restrict__ Wih_e,
                           const float* __restrict__ bih_e) {
    __shared__ float xr[PP];
    int b = blockIdx.x, l = blockIdx.y, tid = threadIdx.x;
    if (tid < PP) xr[tid] = X[b * (TT * PP) + l * PP + tid];
    __syncthreads();
#pragma unroll
    for (int g = 0; g < 3; ++g) {
        int k = g * HH + tid;
        float a = bih_e[k];
        const float* w = Wih_e + k * PP;
#pragma unroll
        for (int i = 0; i < PP; i += 4) {
            float4 wv = *(const float4*)(w + i);
            a += wv.x * xr[i] + wv.y * xr[i + 1] + wv.z * xr[i + 2] + wv.w * xr[i + 3];
        }
        g_xpe[(l * BB + b) * K3H + k] = a;
    }
}

// ---- encoder GRU scan -----------------------------------------------------------------
__global__ void enc_kernel(const float* __restrict__ Whh_e,
                           const float* __restrict__ bhh_e) {
    __shared__ float hs[HH];
    int b = blockIdx.x, j = threadIdx.x;
    hs[j] = 0.0f;
    float bR = bhh_e[j], bZ = bhh_e[HH + j], bN = bhh_e[2 * HH + j];
    const float* wR = Whh_e + j * HH;
    const float* wZ = Whh_e + (HH + j) * HH;
    const float* wN = Whh_e + (2 * HH + j) * HH;
    __syncthreads();
    for (int l = 0; l < LE; ++l) {
        float aR = 0.f, aZ = 0.f, aN = 0.f;
#pragma unroll 8
        for (int h = 0; h < HH; h += 4) {
            float4 hv = *(const float4*)&hs[h];
            float4 r4 = *(const float4*)(wR + h);
            float4 z4 = *(const float4*)(wZ + h);
            float4 n4 = *(const float4*)(wN + h);
            aR += r4.x * hv.x + r4.y * hv.y + r4.z * hv.z + r4.w * hv.w;
            aZ += z4.x * hv.x + z4.y * hv.y + z4.z * hv.z + z4.w * hv.w;
            aN += n4.x * hv.x + n4.y * hv.y + n4.z * hv.z + n4.w * hv.w;
        }
        const float* xp = g_xpe + (l * BB + b) * K3H;
        float r = sigf(xp[j] + aR + bR);
        float z = sigf(xp[HH + j] + aZ + bZ);
        float n = tfast(xp[2 * HH + j] + r * (aN + bN));
        float hold = hs[j];
        __syncthreads();
        hs[j] = (1.0f - z) * n + z * hold;
        __syncthreads();
    }
    g_hT[b * HH + j] = hs[j];
}

// ---- mu / log_var / z ---------------------------------------------------------------------
__global__ void muz_kernel(const float* __restrict__ Wmu, const float* __restrict__ bmu,
                           const float* __restrict__ Wstd, const float* __restrict__ bstd,
                           const float* __restrict__ eps, float* __restrict__ out) {
    __shared__ float hs[HH];
    int b = blockIdx.x, j = threadIdx.x;
    hs[j] = g_hT[b * HH + j];
    __syncthreads();
    float am = bmu[j], as = bstd[j];
    const float* wm = Wmu + j * HH;
    const float* ws = Wstd + j * HH;
#pragma unroll 8
    for (int h = 0; h < HH; h += 4) {
        float4 hv = *(const float4*)&hs[h];
        float4 m4 = *(const float4*)(wm + h);
        float4 s4 = *(const float4*)(ws + h);
        am += m4.x * hv.x + m4.y * hv.y + m4.z * hv.z + m4.w * hv.w;
        as += s4.x * hv.x + s4.y * hv.y + s4.z * hv.z + s4.w * hv.w;
    }
    out[MU_OFF + b * HH + j] = am;
    out[LV_OFF + b * HH + j] = as;
    g_z[b * HH + j] = am + expf(0.5f * as) * eps[b * HH + j];
}

// ---- decoder: mma.sync bf16 split-2, 128 CTAs = (p, b-half) ---------------------------------
extern __shared__ unsigned char smem[];

__global__ void __launch_bounds__(288, 1) dec_kernel(
    const float* __restrict__ bih_d, const float* __restrict__ bhh_d,
    const float* __restrict__ Wlin, const float* __restrict__ blin,
    float* __restrict__ out) {
    const int tid = threadIdx.x;
    const int p = blockIdx.x >> 1, bhalf = blockIdx.x & 1;
    const int w = tid >> 5, lane = tid & 31;
    const int wc = w - 1;                 // consumer warp id 0..7 (w>=1)
    const int g = lane >> 2, tig = lane & 3;
    const uint32_t sb = s2u(smem);
    float* red = (float*)(smem + RED_OFF);

    if (tid == 0) {
#pragma unroll
        for (int s = 0; s < RING; ++s) {
            mbar_init(sb + FULL_OFF + s * 8, 1);
            mbar_init(sb + EMPTY_OFF + s * 8, 8);
        }
        asm volatile("fence.proxy.async.shared::cta;" ::: "memory");
    }

    // per-thread constants + h registers (consumers only)
    const int jw = wc * 32;
    float bRv[2][2], bZv[2][2], bNxv[2][2], bNhv[2][2], wlv[2][2];
    float hreg[16];
    if (wc >= 0) {
#pragma unroll
        for (int mt = 0; mt < 2; ++mt)
#pragma unroll
            for (int rr = 0; rr < 2; ++rr) {
                int j = jw + mt * 16 + g + rr * 8;
                bRv[mt][rr]  = bih_d[p * K3H + j] + bhh_d[p * K3H + j];
                bZv[mt][rr]  = bih_d[p * K3H + 256 + j] + bhh_d[p * K3H + 256 + j];
                bNxv[mt][rr] = bih_d[p * K3H + 512 + j];
                bNhv[mt][rr] = bhh_d[p * K3H + 512 + j];
                wlv[mt][rr]  = Wlin[p * HH + j];
            }
#pragma unroll
        for (int mt = 0; mt < 2; ++mt)
#pragma unroll
            for (int nt = 0; nt < 2; ++nt)
#pragma unroll
                for (int rr = 0; rr < 2; ++rr)
#pragma unroll
                    for (int cc = 0; cc < 2; ++cc) {
                        int j = jw + mt * 16 + g + rr * 8;
                        int bcol = nt * 8 + 2 * tig + cc;
                        hreg[(mt * 2 + nt) * 4 + rr * 2 + cc] =
                            g_z[(bhalf * 16 + bcol) * HH + j];
                    }
        // init v h-region (ct = 0..255 covers j)
        int ct = tid - 32;
        for (int b = 0; b < 16; ++b) {
            float v = g_z[(bhalf * 16 + b) * HH + ct];
            __nv_bfloat16 hi = __float2bfloat16(v);
            __nv_bfloat16 lo = __float2bfloat16(v - __bfloat162float(hi));
            uint32_t ad = (uint32_t)((ct >> 1) * 16 + b) * 4 + (ct & 1) * 2;
            *(__nv_bfloat16*)(smem + VHI_OFF + ad) = hi;
            *(__nv_bfloat16*)(smem + VLO_OFF + ad) = lo;
        }
        // x words for step 0
        {
            const uint32_t* src = g_Xpk + (0 * 2 + bhalf) * 1024;
#pragma unroll
            for (int q = 0; q < 2; ++q) {
                int widx = ct * 2 + q;
                *(uint32_t*)(smem + VHI_OFF + (2048 + widx) * 4) = src[widx];
                *(uint32_t*)(smem + VLO_OFF + (2048 + widx) * 4) = src[512 + widx];
            }
        }
    }
    const float blin_p = blin[p];
    __syncthreads();

    const uint32_t laneoff = (uint32_t)((((lane >> 3) & 1) * 8 + (lane & 7)) * 32 +
                                        ((lane >> 4) & 1) * 16);
    const unsigned char* wsrc = g_Wpk + (size_t)p * NCH * CHUNK_BYTES;

    for (int l = 0; l < LSTEPS; ++l) {
        if (w == 0) {
            // ---------------- producer warp ----------------
            if (lane == 0) {
                for (int c = 0; c < NCH; ++c) {
                    int n = l * NCH + c, s = n & 3;
                    mwait(sb + EMPTY_OFF + s * 8, (uint32_t)(((n >> 2) + 1) & 1));
                    mbar_expect(sb + FULL_OFF + s * 8, CHUNK_BYTES);
                    bulk_cp(sb + RING_OFF + s * CHUNK_BYTES,
                            wsrc + (size_t)c * CHUNK_BYTES, CHUNK_BYTES,
                            sb + FULL_OFF + s * 8);
                }
            }
            __syncthreads();   // bar1
            __syncthreads();   // bar2
        } else {
            // ---------------- consumer warps ----------------
            float accR[2][2][4], accZ[2][2][4], accNh[2][2][4], accNx[2][2][4];
#pragma unroll
            for (int mt = 0; mt < 2; ++mt)
#pragma unroll
                for (int nt = 0; nt < 2; ++nt)
#pragma unroll
                    for (int q = 0; q < 4; ++q) {
                        accR[mt][nt][q] = 0.f; accZ[mt][nt][q] = 0.f;
                        accNh[mt][nt][q] = 0.f; accNx[mt][nt][q] = 0.f;
                    }

#pragma unroll 1
            for (int c = 0; c < NCH; ++c) {
                int n = l * NCH + c, s = n & 3;
                mwait(sb + FULL_OFF + s * 8, (uint32_t)((n >> 2) & 1));

                // B fragments from v (hi/lo)
                uint32_t bh[2][2], bl[2][2];
#pragma unroll
                for (int hf = 0; hf < 2; ++hf)
#pragma unroll
                    for (int nt = 0; nt < 2; ++nt) {
                        uint32_t wo = (uint32_t)((8 * c + hf * 4 + tig) * 16 +
                                                 nt * 8 + g) * 4;
                        bh[hf][nt] = *(const uint32_t*)(smem + VHI_OFF + wo);
                        bl[hf][nt] = *(const uint32_t*)(smem + VLO_OFF + wo);
                    }

                uint32_t tb = sb + RING_OFF + s * CHUNK_BYTES + wc * 6144 + laneoff;
#pragma unroll
                for (int mt = 0; mt < 2; ++mt) {
#pragma unroll
                    for (int gate = 0; gate < 3; ++gate) {
                        uint32_t ahi[4], alo[4];
                        lm4(ahi, tb + mt * 3072 + gate * 1024);
                        lm4(alo, tb + mt * 3072 + gate * 1024 + 512);
                        float (*acc)[4] =
                            (gate == 0) ? accR[mt] :
                            (gate == 1) ? accZ[mt] :
                            (c < 16 ? accNh[mt] : accNx[mt]);
#pragma unroll
                        for (int nt = 0; nt < 2; ++nt) {
                            mma16816(acc[nt], ahi, bh[0][nt], bh[1][nt]);
                            mma16816(acc[nt], ahi, bl[0][nt], bl[1][nt]);
                            mma16816(acc[nt], alo, bh[0][nt], bh[1][nt]);
                        }
                    }
                }
                if (lane == 0) mbar_arrive(sb + EMPTY_OFF + s * 8);
            }
            __syncthreads();   // bar1: all v reads for step l done

            // ---------------- epilogue ----------------
            float part[4] = {0.f, 0.f, 0.f, 0.f};
#pragma unroll
            for (int mt = 0; mt < 2; ++mt)
#pragma unroll
                for (int nt = 0; nt < 2; ++nt)
#pragma unroll
                    for (int rr = 0; rr < 2; ++rr)
#pragma unroll
                        for (int cc = 0; cc < 2; ++cc) {
                            int q = rr * 2 + cc;
                            float r = sigf(accR[mt][nt][q] + bRv[mt][rr]);
                            float z = sigf(accZ[mt][nt][q] + bZv[mt][rr]);
                            float nn = tfast(accNx[mt][nt][q] + bNxv[mt][rr] +
                                             r * (accNh[mt][nt][q] + bNhv[mt][rr]));
                            int hix = (mt * 2 + nt) * 4 + q;
                            float hn = nn + z * (hreg[hix] - nn);
                            hreg[hix] = hn;
                            int j = jw + mt * 16 + g + rr * 8;
                            int bcol = nt * 8 + 2 * tig + cc;
                            __nv_bfloat16 hi = __float2bfloat16(hn);
                            __nv_bfloat16 lo =
                                __float2bfloat16(hn - __bfloat162float(hi));
                            uint32_t ad = (uint32_t)((j >> 1) * 16 + bcol) * 4 +
                                          (j & 1) * 2;
                            *(__nv_bfloat16*)(smem + VHI_OFF + ad) = hi;
                            *(__nv_bfloat16*)(smem + VLO_OFF + ad) = lo;
                            part[nt * 2 + cc] += hn * wlv[mt][rr];
                        }
            // x words for step l+1
            if (l + 1 < LSTEPS) {
                int ct = tid - 32;
                const uint32_t* src = g_Xpk + ((l + 1) * 2 + bhalf) * 1024;
#pragma unroll
                for (int q = 0; q < 2; ++q) {
                    int widx = ct * 2 + q;
                    *(uint32_t*)(smem + VHI_OFF + (2048 + widx) * 4) = src[widx];
                    *(uint32_t*)(smem + VLO_OFF + (2048 + widx) * 4) = src[512 + widx];
                }
            }
            // Wlin reduction over j
#pragma unroll
            for (int off = 16; off >= 4; off >>= 1)
#pragma unroll
                for (int q = 0; q < 4; ++q)
                    part[q] += __shfl_down_sync(0xffffffffu, part[q], off);
            if (lane < 4) {
#pragma unroll
                for (int nt = 0; nt < 2; ++nt)
#pragma unroll
                    for (int cc = 0; cc < 2; ++cc)
                        red[wc * 16 + nt * 8 + 2 * lane + cc] = part[nt * 2 + cc];
            }
            __syncthreads();   // bar2
            if (w == 1 && lane < 16) {
                float s = blin_p;
#pragma unroll
                for (int ww = 0; ww < 8; ++ww) s += red[ww * 16 + lane];
                out[(p * BB + bhalf * 16 + lane) * LSTEPS + l] = s;
            }
        }
    }
}

// -------------------------------------------------------------------------------------------
extern "C" void kernel_launch(void* const* d_in, const int* in_sizes, int n_in,
                              void* d_out, int out_size) {
    const float* X     = (const float*)d_in[0];
    const float* eps   = (const float*)d_in[1];
    const float* Wih_e = (const float*)d_in[3];
    const float* Whh_e = (const float*)d_in[4];
    const float* bih_e = (const float*)d_in[5];
    const float* bhh_e = (const float*)d_in[6];
    const float* Wmu   = (const float*)d_in[7];
    const float* bmu   = (const float*)d_in[8];
    const float* Wstd  = (const float*)d_in[9];
    const float* bstd  = (const float*)d_in[10];
    const float* Wih_d = (const float*)d_in[11];
    const float* Whh_d = (const float*)d_in[12];
    const float* bih_d = (const float*)d_in[13];
    const float* bhh_d = (const float*)d_in[14];
    const float* Wlin  = (const float*)d_in[15];
    const float* blin  = (const float*)d_in[16];
    float* out = (float*)d_out;

    static int smem_set = 0;
    if (!smem_set) {
        cudaFuncSetAttribute(dec_kernel, cudaFuncAttributeMaxDynamicSharedMemorySize,
                             SMEM_TOTAL);
        smem_set = 1;
    }

    packW_kernel<<<dim3(PP, NCH), 256>>>(Whh_d, Wih_d);
    packX_kernel<<<LSTEPS, 256>>>(X);
    xpe_kernel<<<dim3(BB, LE), 256>>>(X, Wih_e, bih_e);
    enc_kernel<<<BB, 256>>>(Whh_e, bhh_e);
    muz_kernel<<<BB, 256>>>(Wmu, bmu, Wstd, bstd, eps, out);
    dec_kernel<<<2 * PP, 288, SMEM_TOTAL>>>(bih_d, bhh_d, Wlin, blin, out);
}